// round 3
// baseline (speedup 1.0000x reference)
#include <cuda_runtime.h>

typedef unsigned long long u64;

#define NTOK 8192
#define KTOP 4
#define BW   16
#define DD   512
#define ME   64
#define NK   (NTOK*KTOP)        // 32768
#define UROWS 513               // D+1
#define NDTOT (NTOK*DD)         // 4194304
#define INV_NKB (1.0f/((float)NTOK*KTOP*BW))

// ---------------- scratch (static device globals; no runtime alloc) -----------
__device__ float g_rinv[ME*BW];       // per (expert, b) inverse column norm
__device__ int   g_cnt[ME];
__device__ int   g_off[ME];
__device__ int   g_base[ME+1];
__device__ int   g_plist[NK];         // pair ids bucketed by expert
__device__ float g_pw[NK*DD];         // per-(n,k) partial writes, 67MB (L2-resident)

// ---------------- packed f32x2 helpers (sm_103a) ------------------------------
__device__ __forceinline__ u64 pack2(float x, float y) {
    u64 r; asm("mov.b64 %0, {%1,%2};" : "=l"(r) : "f"(x), "f"(y)); return r;
}
__device__ __forceinline__ void fma2(u64& d, u64 a, u64 b) {
    asm("fma.rn.f32x2 %0, %1, %2, %0;" : "+l"(d) : "l"(a), "l"(b));
}
__device__ __forceinline__ float2 unpack2(u64 v) {
    float2 f; asm("mov.b64 {%0,%1}, %2;" : "=f"(f.x), "=f"(f.y) : "l"(v)); return f;
}

// ---------------- kernel A: column norms -> rinv; also zero g_cnt -------------
__global__ void k_norm(const float* __restrict__ U) {
    int m = blockIdx.x, t = threadIdx.x;
    if (t == 0) g_cnt[m] = 0;
    const float* Um = U + (size_t)m * UROWS * BW;
    int b = t & 15, g = t >> 4;
    float s = 0.f;
    for (int d = g; d < UROWS; d += 16) { float v = Um[d*BW + b]; s += v*v; }
    __shared__ float red[256];
    red[t] = s; __syncthreads();
    #pragma unroll
    for (int o = 128; o >= 16; o >>= 1) { if (t < o) red[t] += red[t+o]; __syncthreads(); }
    if (t < 16) g_rinv[m*BW + t] = rsqrtf(red[t]);
}

// ---------------- kernel E1: expert histogram ---------------------------------
__global__ void k_hist(const int* __restrict__ idx) {
    __shared__ int lh[ME];
    int t = threadIdx.x;
    if (t < ME) lh[t] = 0;
    __syncthreads();
    int p = blockIdx.x * 512 + t;
    atomicAdd(&lh[idx[p]], 1);
    __syncthreads();
    if (t < ME) atomicAdd(&g_cnt[t], lh[t]);
}

// ---------------- kernel E2: exclusive prefix ---------------------------------
__global__ void k_scan() {
    __shared__ int s[ME];
    int t = threadIdx.x;
    s[t] = g_cnt[t];
    __syncthreads();
    if (t == 0) {
        int run = 0;
        for (int m = 0; m < ME; m++) { int c = s[m]; g_base[m] = run; g_off[m] = run; run += c; }
        g_base[ME] = run;
    }
}

// ---------------- kernel E3: scatter pair ids into expert buckets -------------
__global__ void k_scatter(const int* __restrict__ idx) {
    int p = blockIdx.x * 512 + threadIdx.x;
    int m = idx[p];
    int pos = atomicAdd(&g_off[m], 1);
    g_plist[pos] = p;
}

// ---------------- kernel B: stage 1 (pw[p][d] = Un[e_p] @ h_p) ---------------
// grid = ME*4 (expert x quarter-list), block = 128. Thread t owns d = 4t..4t+3.
// 8 pairs register-blocked; U chunk in SMEM [b][d]; h pre-duplicated as f32x2.
__global__ __launch_bounds__(128) void k_stage1(const float* __restrict__ hs,
                                                const float* __restrict__ U) {
    const int m = blockIdx.x >> 2, s = blockIdx.x & 3;
    const int t = threadIdx.x;
    __shared__ float Us[BW*DD];       // 32KB, [b][d]
    __shared__ u64   h2s[64*BW];      // 8KB, pre-duplicated {h,h}
    __shared__ int   list_s[64];
    __shared__ float rv[BW];
    if (t < BW) rv[t] = g_rinv[m*BW + t];
    __syncthreads();
    const float4* Um4 = (const float4*)(U + (size_t)m * UROWS * BW);
    for (int q = t; q < DD*BW/4; q += 128) {
        float4 v = Um4[q];
        int d = q >> 2, b0 = (q & 3) * 4;
        Us[(b0+0)*DD + d] = v.x * rv[b0+0];
        Us[(b0+1)*DD + d] = v.y * rv[b0+1];
        Us[(b0+2)*DD + d] = v.z * rv[b0+2];
        Us[(b0+3)*DD + d] = v.w * rv[b0+3];
    }
    int lo = g_base[m], hi = g_base[m+1], len = hi - lo;
    int j0 = lo + (len * s) / 4, j1 = lo + (len * (s+1)) / 4;

    for (int cb = j0; cb < j1; cb += 64) {
        int cn = min(64, j1 - cb);
        __syncthreads();                      // protect list_s/h2s reuse
        if (t < cn) list_s[t] = g_plist[cb + t];
        __syncthreads();
        for (int i = t; i < cn*BW; i += 128) {
            int pr = list_s[i >> 4];
            float v = hs[pr*BW + (i & 15)];
            h2s[i] = pack2(v, v);
        }
        __syncthreads();
        for (int pb = 0; pb < cn; pb += 8) {
            int qi[8];
            #pragma unroll
            for (int q = 0; q < 8; q++) qi[q] = min(pb + q, cn - 1);
            u64 a0[8], a1[8];
            #pragma unroll
            for (int q = 0; q < 8; q++) { a0[q] = 0ull; a1[q] = 0ull; }
            #pragma unroll
            for (int b = 0; b < BW; b++) {
                float4 u = *(const float4*)&Us[b*DD + t*4];
                u64 u01 = pack2(u.x, u.y), u23 = pack2(u.z, u.w);
                #pragma unroll
                for (int q = 0; q < 8; q++) {
                    u64 h2 = h2s[qi[q]*BW + b];
                    fma2(a0[q], u01, h2);
                    fma2(a1[q], u23, h2);
                }
            }
            #pragma unroll
            for (int q = 0; q < 8; q++) {
                int pr = list_s[qi[q]];        // tail duplicates write same value: benign
                float2 x = unpack2(a0[q]), y = unpack2(a1[q]);
                *(float4*)&g_pw[(size_t)pr*DD + t*4] = make_float4(x.x, x.y, y.x, y.y);
            }
        }
    }
}

// ---------------- kernel C: writes[n][d] = sum_k pw[n][k][d]; zero loss -------
__global__ void k_reduce(float* __restrict__ out) {
    int e = blockIdx.x * 256 + threadIdx.x;   // quad index over N*128
    const float4* pw4 = (const float4*)g_pw;
    int n = e >> 7, dq = e & 127;
    size_t bq = (size_t)n * 4 * 128 + dq;
    float4 a = pw4[bq], b = pw4[bq + 128], c = pw4[bq + 256], d = pw4[bq + 384];
    float4 r = make_float4(a.x+b.x+c.x+d.x, a.y+b.y+c.y+d.y,
                           a.z+b.z+c.z+d.z, a.w+b.w+c.w+d.w);
    ((float4*)out)[(size_t)n*128 + dq] = r;
    if (e == 0) out[NDTOT] = 0.f;
}

// ---------------- kernel D: stage 2 recon + loss ------------------------------
// grid = ME*2, block = 256 (8 warps). Warp handles 4 pairs at a time.
// Lane: b = l&15, half = l>>4 owns 256 contiguous d. Ut in SMEM [b][514-pad].
__global__ __launch_bounds__(256) void k_stage2(const float* __restrict__ hs,
                                                const float* __restrict__ U,
                                                float* __restrict__ out) {
    extern __shared__ float dsm[];
    float* Ut = dsm;                 // 16*514 floats
    float* ws = dsm + BW*514;        // 8 warps * 4 pairs * 512 floats
    const int m = blockIdx.x >> 1, s = blockIdx.x & 1;
    const int t = threadIdx.x, w = t >> 5, l = t & 31;
    const int b = l & 15, half = l >> 4;
    __shared__ float rv[BW];
    if (t < BW) rv[t] = g_rinv[m*BW + t];
    __syncthreads();
    const float4* Um4 = (const float4*)(U + (size_t)m * UROWS * BW);
    for (int q = t; q < DD*BW/4; q += 256) {
        float4 v = Um4[q];
        int d = q >> 2, b0 = (q & 3) * 4;
        Ut[(b0+0)*514 + d] = v.x * rv[b0+0];
        Ut[(b0+1)*514 + d] = v.y * rv[b0+1];
        Ut[(b0+2)*514 + d] = v.z * rv[b0+2];
        Ut[(b0+3)*514 + d] = v.w * rv[b0+3];
    }
    __syncthreads();
    int lo = g_base[m], hi = g_base[m+1], len = hi - lo;
    int j0 = lo + (len * s) / 2, j1 = lo + (len * (s+1)) / 2;
    float lloss = 0.f;
    float* mws = ws + w * (4*DD);
    const float* utb = Ut + b*514 + half*256;

    for (int jb = j0 + w*4; jb < j1; jb += 32) {
        int pr[4]; float hv[4];
        #pragma unroll
        for (int q = 0; q < 4; q++) {
            int jq = min(jb + q, j1 - 1);
            pr[q] = g_plist[jq];
        }
        #pragma unroll
        for (int q = 0; q < 4; q++) {
            const float4* src = (const float4*)(out + (size_t)(pr[q] >> 2) * DD);
            float4* dst = (float4*)(mws + q*DD);
            #pragma unroll
            for (int r = 0; r < 4; r++) dst[r*32 + l] = src[r*32 + l];
            hv[q] = hs[pr[q]*BW + b];
        }
        __syncwarp();
        u64 acc[4] = {0ull,0ull,0ull,0ull};
        const float* wb = mws + half*256;
        #pragma unroll 8
        for (int i = 0; i < 128; i++) {
            u64 u2 = *(const u64*)(utb + 2*i);
            fma2(acc[0], u2, *(const u64*)(wb + 0*DD + 2*i));
            fma2(acc[1], u2, *(const u64*)(wb + 1*DD + 2*i));
            fma2(acc[2], u2, *(const u64*)(wb + 2*DD + 2*i));
            fma2(acc[3], u2, *(const u64*)(wb + 3*DD + 2*i));
        }
        #pragma unroll
        for (int q = 0; q < 4; q++) {
            float2 a = unpack2(acc[q]);
            float v = a.x + a.y;
            v += __shfl_xor_sync(0xffffffffu, v, 16);
            float diff = v - hv[q];
            if (half == 0 && (jb + q) < j1) lloss += diff * diff;  // guard tail dups
        }
        __syncwarp();
    }
    __syncthreads();                 // done with Ut/ws; reuse dsm for reduction
    dsm[t] = lloss;
    __syncthreads();
    for (int o = 128; o > 0; o >>= 1) { if (t < o) dsm[t] += dsm[t+o]; __syncthreads(); }
    if (t == 0) atomicAdd(out + NDTOT, dsm[0] * INV_NKB);
}

// ---------------- launch ------------------------------------------------------
extern "C" void kernel_launch(void* const* d_in, const int* in_sizes, int n_in,
                              void* d_out, int out_size) {
    const float* hs = nullptr; const int* idx = nullptr; const float* U = nullptr;
    for (int i = 0; i < n_in; i++) {
        if      (in_sizes[i] == NTOK*KTOP*BW) hs  = (const float*)d_in[i];
        else if (in_sizes[i] == NK)           idx = (const int*)d_in[i];
        else if (in_sizes[i] == ME*UROWS*BW)  U   = (const float*)d_in[i];
    }
    float* out = (float*)d_out;

    k_norm   <<<ME, 256>>>(U);
    k_hist   <<<NK/512, 512>>>(idx);
    k_scan   <<<1, ME>>>();
    k_scatter<<<NK/512, 512>>>(idx);
    k_stage1 <<<ME*4, 128>>>(hs, U);
    k_reduce <<<NDTOT/1024, 256>>>(out);
    const int smemD = (BW*514 + 8*4*DD) * (int)sizeof(float);   // 98432 B
    cudaFuncSetAttribute(k_stage2, cudaFuncAttributeMaxDynamicSharedMemorySize, smemD);
    k_stage2 <<<ME*2, 256, smemD>>>(hs, U, out);
}